// round 5
// baseline (speedup 1.0000x reference)
#include <cuda_runtime.h>
#include <cuda_bf16.h>
#include <cstdint>

// ============================================================================
// GraphSAGE 2-layer (mean aggr), fp32.
//   t1 = x@W1l^T ; xr = x@W1r^T           (fused dual-output GEMM, TN=256)
//   agg1[dst] += t1[src]; cnt[dst]++      (vector-atomic scatter)
//   h  = relu(agg1/max(cnt,1) + b1 + xr)  (elementwise)
//   t2 = h@W2l^T ; hr = h@W2r^T           (fused dual-output GEMM, TN=128)
//   agg2[dst] += t2[src]
//   out = agg2/max(cnt,1) + b2 + hr       (elementwise)
// edge_index is int32 on device (JAX x64 disabled).
// ============================================================================

#define NN 100000
#define KD 128

// Scratch: [agg1:128][agg2:64][cnt:1][t1:128][xr/h:128][t2:64][hr:64] per node
// + transposed weights Wt1 (128x256), Wt2 (128x128) at the end.
__device__ float g_buf[(size_t)NN * 577 + 49152];

static constexpr size_t OFF_AGG1 = 0;
static constexpr size_t OFF_AGG2 = (size_t)NN * 128;
static constexpr size_t OFF_CNT  = (size_t)NN * 192;
static constexpr size_t OFF_T1   = (size_t)NN * 193;
static constexpr size_t OFF_XR   = (size_t)NN * 321;   // becomes h in-place
static constexpr size_t OFF_T2   = (size_t)NN * 449;
static constexpr size_t OFF_HR   = (size_t)NN * 513;
static constexpr size_t OFF_WT1  = (size_t)NN * 577;            // 128*256
static constexpr size_t OFF_WT2  = OFF_WT1 + 128 * 256;         // 128*128

// ----------------------------------------------------------------------------
__global__ __launch_bounds__(256) void zero_kernel(int n4) {
    int i = blockIdx.x * 256 + threadIdx.x;
    if (i < n4)
        reinterpret_cast<float4*>(g_buf)[i] = make_float4(0.f, 0.f, 0.f, 0.f);
}

// Transpose + stack two [TNH,128] weights into Wt[k][2*TNH] (K-major).
template <int TNH>  // half-width: 128 (layer1) or 64 (layer2)
__global__ __launch_bounds__(256) void transpose_w(
    const float* __restrict__ Wa, const float* __restrict__ Wb,
    float* __restrict__ Wt)
{
    constexpr int TN = 2 * TNH;
    int i = blockIdx.x * 256 + threadIdx.x;
    if (i >= 128 * TN) return;
    int k = i / TN;
    int col = i % TN;
    float v = (col < TNH) ? Wa[col * 128 + k] : Wb[(col - TNH) * 128 + k];
    Wt[i] = v;
}

// ----------------------------------------------------------------------------
__device__ __forceinline__ void red_add_v4(float* p, float4 v) {
    asm volatile("red.global.add.v4.f32 [%0], {%1, %2, %3, %4};"
                 :: "l"(p), "f"(v.x), "f"(v.y), "f"(v.z), "f"(v.w)
                 : "memory");
}

template <int DIM, bool DO_CNT>
__global__ __launch_bounds__(256) void scatter_kernel(
    const float* __restrict__ t,
    const int* __restrict__ src,
    const int* __restrict__ dst,
    float* __restrict__ agg,
    float* __restrict__ cnt,
    int E)
{
    constexpr int LPE = DIM / 4;
    long long gid = (long long)blockIdx.x * 256 + threadIdx.x;
    long long e = gid / LPE;
    int lane = (int)(gid % LPE);
    if (e >= E) return;
    int s = src[e];
    int d = dst[e];
    float4 v = *reinterpret_cast<const float4*>(t + (long long)s * DIM + lane * 4);
    red_add_v4(agg + (long long)d * DIM + lane * 4, v);
    if (DO_CNT && lane == 0) atomicAdd(cnt + d, 1.0f);
}

// ----------------------------------------------------------------------------
// Fused dual-output GEMM:  [outA | outB] = A[M,128] @ Wt^T-stacked
// Wt is K-major [128][TN] (pre-transposed). TM=128 rows/block, 256 threads,
// per-thread tile 8 x (TN/16). FFMA-bound: per k = 6 LDS.128 vs 128 FFMA.
// ----------------------------------------------------------------------------
template <int TN>
__global__ __launch_bounds__(256, 1) void gemm_dual(
    const float* __restrict__ A,
    const float* __restrict__ Wt,
    float* __restrict__ outA,
    float* __restrict__ outB,
    int M)
{
    constexpr int TM = 128;
    constexpr int ASR = TM + 4;        // 132: float4-aligned, 2-way store conflict only
    constexpr int CPT = TN / 16;       // cols per thread: 16 or 8
    constexpr int NG = CPT / 4;        // float4 groups: 4 or 2
    constexpr int TNH = TN / 2;

    extern __shared__ float smem[];
    float* A_s = smem;                 // K-major: [k][ASR]
    float* W_s = smem + 128 * ASR;     // K-major: [k][TN]

    const int t = threadIdx.x;
    const int row0 = blockIdx.x * TM;

    // Stage A: coalesced float4 global loads, scalar transposed stores.
    {
        const float4* A4 = reinterpret_cast<const float4*>(A);
        for (int idx4 = t; idx4 < TM * 32; idx4 += 256) {
            int row = idx4 >> 5;
            int k4 = idx4 & 31;
            float4 v = make_float4(0.f, 0.f, 0.f, 0.f);
            int grow = row0 + row;
            if (grow < M) v = A4[(long long)grow * 32 + k4];
            A_s[(4 * k4 + 0) * ASR + row] = v.x;
            A_s[(4 * k4 + 1) * ASR + row] = v.y;
            A_s[(4 * k4 + 2) * ASR + row] = v.z;
            A_s[(4 * k4 + 3) * ASR + row] = v.w;
        }
    }
    // Stage W: straight float4 copy (Wt already K-major), conflict-free.
    {
        const float4* Wt4 = reinterpret_cast<const float4*>(Wt);
        float4* W_s4 = reinterpret_cast<float4*>(W_s);
        for (int idx4 = t; idx4 < 128 * TN / 4; idx4 += 256)
            W_s4[idx4] = Wt4[idx4];
    }
    __syncthreads();

    const int tcol = t & 15;
    const int trow = t >> 4;           // 0..15
    const int rowbase = trow * 8;

    float acc[8][CPT];
#pragma unroll
    for (int r = 0; r < 8; r++)
#pragma unroll
        for (int c = 0; c < CPT; c++) acc[r][c] = 0.f;

    const float4* As4 = reinterpret_cast<const float4*>(A_s);
    const float4* Ws4 = reinterpret_cast<const float4*>(W_s);

#pragma unroll 2
    for (int k = 0; k < 128; k++) {
        float a[8];
        {
            float4 a0 = As4[k * (ASR / 4) + trow * 2 + 0];  // broadcast
            float4 a1 = As4[k * (ASR / 4) + trow * 2 + 1];
            a[0] = a0.x; a[1] = a0.y; a[2] = a0.z; a[3] = a0.w;
            a[4] = a1.x; a[5] = a1.y; a[6] = a1.z; a[7] = a1.w;
        }
        float w[CPT];
#pragma unroll
        for (int g = 0; g < NG; g++) {
            float4 wv = Ws4[k * (TN / 4) + g * 16 + tcol];
            w[g * 4 + 0] = wv.x; w[g * 4 + 1] = wv.y;
            w[g * 4 + 2] = wv.z; w[g * 4 + 3] = wv.w;
        }
#pragma unroll
        for (int r = 0; r < 8; r++)
#pragma unroll
            for (int c = 0; c < CPT; c++)
                acc[r][c] += a[r] * w[c];
    }

    // Epilogue: thread's cols for group g are [g*64 + tcol*4, +4)
#pragma unroll
    for (int r = 0; r < 8; r++) {
        int row = row0 + rowbase + r;
        if (row >= M) continue;
#pragma unroll
        for (int g = 0; g < NG; g++) {
            int col = g * 64 + tcol * 4;
            float4 v = make_float4(acc[r][g * 4 + 0], acc[r][g * 4 + 1],
                                   acc[r][g * 4 + 2], acc[r][g * 4 + 3]);
            if (col < TNH) {
                *reinterpret_cast<float4*>(outA + (long long)row * TNH + col) = v;
            } else {
                *reinterpret_cast<float4*>(outB + (long long)row * TNH + (col - TNH)) = v;
            }
        }
    }
}

// ----------------------------------------------------------------------------
// Elementwise epilogues.
//   MODE 1: h   = relu(agg/max(cnt,1) + bias + v)   (DIM=128)
//   MODE 2: out =      agg/max(cnt,1) + bias + v    (DIM=64)
// ----------------------------------------------------------------------------
template <int DIM, bool RELU>
__global__ __launch_bounds__(256) void ew_kernel(
    const float* __restrict__ agg,
    const float* __restrict__ cnt,
    const float* __restrict__ bias,
    const float* __restrict__ v,
    float* __restrict__ out,
    int M)
{
    constexpr int Q = DIM / 4;
    long long idx4 = (long long)blockIdx.x * 256 + threadIdx.x;
    if (idx4 >= (long long)M * Q) return;
    int row = (int)(idx4 / Q);
    int c4 = (int)(idx4 % Q);
    float ic = 1.f / fmaxf(cnt[row], 1.f);
    float4 ag = reinterpret_cast<const float4*>(agg)[idx4];
    float4 vv = reinterpret_cast<const float4*>(v)[idx4];
    float4 bb = reinterpret_cast<const float4*>(bias)[c4];
    float4 r;
    r.x = ag.x * ic + bb.x + vv.x;
    r.y = ag.y * ic + bb.y + vv.y;
    r.z = ag.z * ic + bb.z + vv.z;
    r.w = ag.w * ic + bb.w + vv.w;
    if (RELU) {
        r.x = fmaxf(r.x, 0.f); r.y = fmaxf(r.y, 0.f);
        r.z = fmaxf(r.z, 0.f); r.w = fmaxf(r.w, 0.f);
    }
    reinterpret_cast<float4*>(out)[idx4] = r;
}

// ----------------------------------------------------------------------------
extern "C" void kernel_launch(void* const* d_in, const int* in_sizes, int n_in,
                              void* d_out, int out_size)
{
    const float* x   = (const float*)d_in[0];
    const int*   ei  = (const int*)d_in[1];   // int32
    const float* W1l = (const float*)d_in[2];
    const float* b1  = (const float*)d_in[3];
    const float* W1r = (const float*)d_in[4];
    const float* W2l = (const float*)d_in[5];
    const float* b2  = (const float*)d_in[6];
    const float* W2r = (const float*)d_in[7];
    float* out       = (float*)d_out;

    const int M = in_sizes[0] / KD;   // 100000
    const int E = in_sizes[1] / 2;    // 1600000
    const int* src = ei;
    const int* dst = ei + E;

    float* base;
    cudaGetSymbolAddress((void**)&base, g_buf);
    float* agg1 = base + OFF_AGG1;
    float* agg2 = base + OFF_AGG2;
    float* cnt  = base + OFF_CNT;
    float* t1   = base + OFF_T1;
    float* xr   = base + OFF_XR;   // then h (in-place)
    float* t2   = base + OFF_T2;
    float* hr   = base + OFF_HR;
    float* Wt1  = base + OFF_WT1;
    float* Wt2  = base + OFF_WT2;

    constexpr int SMEM256 = (128 * 132 + 128 * 256) * 4;  // 198,656 B
    constexpr int SMEM128 = (128 * 132 + 128 * 128) * 4;  // 133,120 B
    cudaFuncSetAttribute(gemm_dual<256>, cudaFuncAttributeMaxDynamicSharedMemorySize, SMEM256);
    cudaFuncSetAttribute(gemm_dual<128>, cudaFuncAttributeMaxDynamicSharedMemorySize, SMEM128);

    const int gblocks = (M + 127) / 128;

    // 1. Zero accumulators (agg1+agg2+cnt contiguous)
    {
        int n4 = (M * 193 + 3) / 4;
        zero_kernel<<<(n4 + 255) / 256, 256>>>(n4);
    }
    // 2. Transpose/stack weights (tiny)
    transpose_w<128><<<(128 * 256 + 255) / 256, 256>>>(W1l, W1r, Wt1);
    transpose_w<64><<<(128 * 128 + 255) / 256, 256>>>(W2l, W2r, Wt2);

    // 3. [t1 | xr] = x @ [W1l; W1r]^T
    gemm_dual<256><<<gblocks, 256, SMEM256>>>(x, Wt1, t1, xr, M);

    // 4. agg1[dst] += t1[src]; cnt[dst] += 1
    {
        long long thr = (long long)E * 32;
        scatter_kernel<128, true><<<(int)((thr + 255) / 256), 256>>>(t1, src, dst, agg1, cnt, E);
    }

    // 5. h = relu(agg1/cnt + b1 + xr)  (in-place into xr)
    {
        long long n4 = (long long)M * 32;
        ew_kernel<128, true><<<(int)((n4 + 255) / 256), 256>>>(agg1, cnt, b1, xr, xr, M);
    }

    // 6. [t2 | hr] = h @ [W2l; W2r]^T
    gemm_dual<128><<<gblocks, 256, SMEM128>>>(xr, Wt2, t2, hr, M);

    // 7. agg2[dst] += t2[src]
    {
        long long thr = (long long)E * 16;
        scatter_kernel<64, false><<<(int)((thr + 255) / 256), 256>>>(t2, src, dst, agg2, nullptr, E);
    }

    // 8. out = agg2/cnt + b2 + hr
    {
        long long n4 = (long long)M * 16;
        ew_kernel<64, false><<<(int)((n4 + 255) / 256), 256>>>(agg2, cnt, b2, hr, out, M);
    }
}

// round 6
// speedup vs baseline: 1.0012x; 1.0012x over previous
#include <cuda_runtime.h>
#include <cuda_bf16.h>
#include <cstdint>

// ============================================================================
// GraphSAGE 2-layer (mean aggr), fp32.
//   t1 = x@W1l^T ; xr = x@W1r^T           (fused dual-output GEMM, TN=256)
//   agg1[dst] += t1[src]; cnt[dst]++      (vector-atomic scatter)
//   h  = relu(agg1/max(cnt,1) + b1 + xr)  (elementwise)
//   t2 = h@W2l^T ; hr = h@W2r^T           (fused dual-output GEMM, TN=128)
//   agg2[dst] += t2[src]
//   out = agg2/max(cnt,1) + b2 + hr       (elementwise)
// edge_index is int32 on device (JAX x64 disabled).
// ============================================================================

#define NN 100000
#define KD 128

// Scratch: [agg1:128][agg2:64][cnt:1][t1:128][xr/h:128][t2:64][hr:64] per node
// + transposed weights Wt1 (128x256), Wt2 (128x128) at the end.
__device__ float g_buf[(size_t)NN * 577 + 49152];

static constexpr size_t OFF_AGG1 = 0;
static constexpr size_t OFF_AGG2 = (size_t)NN * 128;
static constexpr size_t OFF_CNT  = (size_t)NN * 192;
static constexpr size_t OFF_T1   = (size_t)NN * 193;
static constexpr size_t OFF_XR   = (size_t)NN * 321;   // becomes h in-place
static constexpr size_t OFF_T2   = (size_t)NN * 449;
static constexpr size_t OFF_HR   = (size_t)NN * 513;
static constexpr size_t OFF_WT1  = (size_t)NN * 577;            // 128*256
static constexpr size_t OFF_WT2  = OFF_WT1 + 128 * 256;         // 128*128

// ----------------------------------------------------------------------------
__global__ __launch_bounds__(256) void zero_kernel(int n4) {
    int i = blockIdx.x * 256 + threadIdx.x;
    if (i < n4)
        reinterpret_cast<float4*>(g_buf)[i] = make_float4(0.f, 0.f, 0.f, 0.f);
}

// Transpose + stack two [TNH,128] weights into Wt[k][2*TNH] (K-major).
template <int TNH>  // half-width: 128 (layer1) or 64 (layer2)
__global__ __launch_bounds__(256) void transpose_w(
    const float* __restrict__ Wa, const float* __restrict__ Wb,
    float* __restrict__ Wt)
{
    constexpr int TN = 2 * TNH;
    int i = blockIdx.x * 256 + threadIdx.x;
    if (i >= 128 * TN) return;
    int k = i / TN;
    int col = i % TN;
    float v = (col < TNH) ? Wa[col * 128 + k] : Wb[(col - TNH) * 128 + k];
    Wt[i] = v;
}

// ----------------------------------------------------------------------------
__device__ __forceinline__ void red_add_v4(float* p, float4 v) {
    asm volatile("red.global.add.v4.f32 [%0], {%1, %2, %3, %4};"
                 :: "l"(p), "f"(v.x), "f"(v.y), "f"(v.z), "f"(v.w)
                 : "memory");
}

template <int DIM, bool DO_CNT>
__global__ __launch_bounds__(256) void scatter_kernel(
    const float* __restrict__ t,
    const int* __restrict__ src,
    const int* __restrict__ dst,
    float* __restrict__ agg,
    float* __restrict__ cnt,
    int E)
{
    constexpr int LPE = DIM / 4;
    long long gid = (long long)blockIdx.x * 256 + threadIdx.x;
    long long e = gid / LPE;
    int lane = (int)(gid % LPE);
    if (e >= E) return;
    int s = src[e];
    int d = dst[e];
    float4 v = *reinterpret_cast<const float4*>(t + (long long)s * DIM + lane * 4);
    red_add_v4(agg + (long long)d * DIM + lane * 4, v);
    if (DO_CNT && lane == 0) atomicAdd(cnt + d, 1.0f);
}

// ----------------------------------------------------------------------------
// Fused dual-output GEMM:  [outA | outB] = A[M,128] @ Wt^T-stacked
// Wt is K-major [128][TN] (pre-transposed). TM=128 rows/block, 256 threads,
// per-thread tile 8 x (TN/16). FFMA-bound: per k = 6 LDS.128 vs 128 FFMA.
// ----------------------------------------------------------------------------
template <int TN>
__global__ __launch_bounds__(256, 1) void gemm_dual(
    const float* __restrict__ A,
    const float* __restrict__ Wt,
    float* __restrict__ outA,
    float* __restrict__ outB,
    int M)
{
    constexpr int TM = 128;
    constexpr int ASR = TM + 4;        // 132: float4-aligned, 2-way store conflict only
    constexpr int CPT = TN / 16;       // cols per thread: 16 or 8
    constexpr int NG = CPT / 4;        // float4 groups: 4 or 2
    constexpr int TNH = TN / 2;

    extern __shared__ float smem[];
    float* A_s = smem;                 // K-major: [k][ASR]
    float* W_s = smem + 128 * ASR;     // K-major: [k][TN]

    const int t = threadIdx.x;
    const int row0 = blockIdx.x * TM;

    // Stage A: coalesced float4 global loads, scalar transposed stores.
    {
        const float4* A4 = reinterpret_cast<const float4*>(A);
        for (int idx4 = t; idx4 < TM * 32; idx4 += 256) {
            int row = idx4 >> 5;
            int k4 = idx4 & 31;
            float4 v = make_float4(0.f, 0.f, 0.f, 0.f);
            int grow = row0 + row;
            if (grow < M) v = A4[(long long)grow * 32 + k4];
            A_s[(4 * k4 + 0) * ASR + row] = v.x;
            A_s[(4 * k4 + 1) * ASR + row] = v.y;
            A_s[(4 * k4 + 2) * ASR + row] = v.z;
            A_s[(4 * k4 + 3) * ASR + row] = v.w;
        }
    }
    // Stage W: straight float4 copy (Wt already K-major), conflict-free.
    {
        const float4* Wt4 = reinterpret_cast<const float4*>(Wt);
        float4* W_s4 = reinterpret_cast<float4*>(W_s);
        for (int idx4 = t; idx4 < 128 * TN / 4; idx4 += 256)
            W_s4[idx4] = Wt4[idx4];
    }
    __syncthreads();

    const int tcol = t & 15;
    const int trow = t >> 4;           // 0..15
    const int rowbase = trow * 8;

    float acc[8][CPT];
#pragma unroll
    for (int r = 0; r < 8; r++)
#pragma unroll
        for (int c = 0; c < CPT; c++) acc[r][c] = 0.f;

    const float4* As4 = reinterpret_cast<const float4*>(A_s);
    const float4* Ws4 = reinterpret_cast<const float4*>(W_s);

#pragma unroll 2
    for (int k = 0; k < 128; k++) {
        float a[8];
        {
            float4 a0 = As4[k * (ASR / 4) + trow * 2 + 0];  // broadcast
            float4 a1 = As4[k * (ASR / 4) + trow * 2 + 1];
            a[0] = a0.x; a[1] = a0.y; a[2] = a0.z; a[3] = a0.w;
            a[4] = a1.x; a[5] = a1.y; a[6] = a1.z; a[7] = a1.w;
        }
        float w[CPT];
#pragma unroll
        for (int g = 0; g < NG; g++) {
            float4 wv = Ws4[k * (TN / 4) + g * 16 + tcol];
            w[g * 4 + 0] = wv.x; w[g * 4 + 1] = wv.y;
            w[g * 4 + 2] = wv.z; w[g * 4 + 3] = wv.w;
        }
#pragma unroll
        for (int r = 0; r < 8; r++)
#pragma unroll
            for (int c = 0; c < CPT; c++)
                acc[r][c] += a[r] * w[c];
    }

    // Epilogue: thread's cols for group g are [g*64 + tcol*4, +4)
#pragma unroll
    for (int r = 0; r < 8; r++) {
        int row = row0 + rowbase + r;
        if (row >= M) continue;
#pragma unroll
        for (int g = 0; g < NG; g++) {
            int col = g * 64 + tcol * 4;
            float4 v = make_float4(acc[r][g * 4 + 0], acc[r][g * 4 + 1],
                                   acc[r][g * 4 + 2], acc[r][g * 4 + 3]);
            if (col < TNH) {
                *reinterpret_cast<float4*>(outA + (long long)row * TNH + col) = v;
            } else {
                *reinterpret_cast<float4*>(outB + (long long)row * TNH + (col - TNH)) = v;
            }
        }
    }
}

// ----------------------------------------------------------------------------
// Elementwise epilogues.
//   MODE 1: h   = relu(agg/max(cnt,1) + bias + v)   (DIM=128)
//   MODE 2: out =      agg/max(cnt,1) + bias + v    (DIM=64)
// ----------------------------------------------------------------------------
template <int DIM, bool RELU>
__global__ __launch_bounds__(256) void ew_kernel(
    const float* __restrict__ agg,
    const float* __restrict__ cnt,
    const float* __restrict__ bias,
    const float* __restrict__ v,
    float* __restrict__ out,
    int M)
{
    constexpr int Q = DIM / 4;
    long long idx4 = (long long)blockIdx.x * 256 + threadIdx.x;
    if (idx4 >= (long long)M * Q) return;
    int row = (int)(idx4 / Q);
    int c4 = (int)(idx4 % Q);
    float ic = 1.f / fmaxf(cnt[row], 1.f);
    float4 ag = reinterpret_cast<const float4*>(agg)[idx4];
    float4 vv = reinterpret_cast<const float4*>(v)[idx4];
    float4 bb = reinterpret_cast<const float4*>(bias)[c4];
    float4 r;
    r.x = ag.x * ic + bb.x + vv.x;
    r.y = ag.y * ic + bb.y + vv.y;
    r.z = ag.z * ic + bb.z + vv.z;
    r.w = ag.w * ic + bb.w + vv.w;
    if (RELU) {
        r.x = fmaxf(r.x, 0.f); r.y = fmaxf(r.y, 0.f);
        r.z = fmaxf(r.z, 0.f); r.w = fmaxf(r.w, 0.f);
    }
    reinterpret_cast<float4*>(out)[idx4] = r;
}

// ----------------------------------------------------------------------------
extern "C" void kernel_launch(void* const* d_in, const int* in_sizes, int n_in,
                              void* d_out, int out_size)
{
    const float* x   = (const float*)d_in[0];
    const int*   ei  = (const int*)d_in[1];   // int32
    const float* W1l = (const float*)d_in[2];
    const float* b1  = (const float*)d_in[3];
    const float* W1r = (const float*)d_in[4];
    const float* W2l = (const float*)d_in[5];
    const float* b2  = (const float*)d_in[6];
    const float* W2r = (const float*)d_in[7];
    float* out       = (float*)d_out;

    const int M = in_sizes[0] / KD;   // 100000
    const int E = in_sizes[1] / 2;    // 1600000
    const int* src = ei;
    const int* dst = ei + E;

    float* base;
    cudaGetSymbolAddress((void**)&base, g_buf);
    float* agg1 = base + OFF_AGG1;
    float* agg2 = base + OFF_AGG2;
    float* cnt  = base + OFF_CNT;
    float* t1   = base + OFF_T1;
    float* xr   = base + OFF_XR;   // then h (in-place)
    float* t2   = base + OFF_T2;
    float* hr   = base + OFF_HR;
    float* Wt1  = base + OFF_WT1;
    float* Wt2  = base + OFF_WT2;

    constexpr int SMEM256 = (128 * 132 + 128 * 256) * 4;  // 198,656 B
    constexpr int SMEM128 = (128 * 132 + 128 * 128) * 4;  // 133,120 B
    cudaFuncSetAttribute(gemm_dual<256>, cudaFuncAttributeMaxDynamicSharedMemorySize, SMEM256);
    cudaFuncSetAttribute(gemm_dual<128>, cudaFuncAttributeMaxDynamicSharedMemorySize, SMEM128);

    const int gblocks = (M + 127) / 128;

    // 1. Zero accumulators (agg1+agg2+cnt contiguous)
    {
        int n4 = (M * 193 + 3) / 4;
        zero_kernel<<<(n4 + 255) / 256, 256>>>(n4);
    }
    // 2. Transpose/stack weights (tiny)
    transpose_w<128><<<(128 * 256 + 255) / 256, 256>>>(W1l, W1r, Wt1);
    transpose_w<64><<<(128 * 128 + 255) / 256, 256>>>(W2l, W2r, Wt2);

    // 3. [t1 | xr] = x @ [W1l; W1r]^T
    gemm_dual<256><<<gblocks, 256, SMEM256>>>(x, Wt1, t1, xr, M);

    // 4. agg1[dst] += t1[src]; cnt[dst] += 1
    {
        long long thr = (long long)E * 32;
        scatter_kernel<128, true><<<(int)((thr + 255) / 256), 256>>>(t1, src, dst, agg1, cnt, E);
    }

    // 5. h = relu(agg1/cnt + b1 + xr)  (in-place into xr)
    {
        long long n4 = (long long)M * 32;
        ew_kernel<128, true><<<(int)((n4 + 255) / 256), 256>>>(agg1, cnt, b1, xr, xr, M);
    }

    // 6. [t2 | hr] = h @ [W2l; W2r]^T
    gemm_dual<128><<<gblocks, 256, SMEM128>>>(xr, Wt2, t2, hr, M);

    // 7. agg2[dst] += t2[src]
    {
        long long thr = (long long)E * 16;
        scatter_kernel<64, false><<<(int)((thr + 255) / 256), 256>>>(t2, src, dst, agg2, nullptr, E);
    }

    // 8. out = agg2/cnt + b2 + hr
    {
        long long n4 = (long long)M * 16;
        ew_kernel<64, false><<<(int)((n4 + 255) / 256), 256>>>(agg2, cnt, b2, hr, out, M);
    }
}